// round 11
// baseline (speedup 1.0000x reference)
#include <cuda_runtime.h>
#include <cuda_bf16.h>
#include <cstdint>
#include <math.h>

// Problem constants
#define NN 512
#define DIM 384
#define PDIM 128
#define H 8
#define SK 16
#define SV 16
#define PK 4
#define PV 8
#define PROJ_COLS 768           // 128+128+128+96+96+192
#define RES_COLS 1408           // 128 + 192 + 64 + 1024
#define EPSV 1e-8f

__device__ __constant__ float kScaleScalar = 0.14433756729740643f;  // (3*16)^-0.5
__device__ __constant__ float kScalePoint  = 0.13608276348795434f;  // (3*4*4.5)^-0.5
__device__ __constant__ float kScalePair   = 0.57735026918962576f;  // 3^-0.5

// Scratch (allocation-free contract: __device__ globals)
__device__ float g_Wcat[DIM * PROJ_COLS];
__device__ float g_proj[NN * PROJ_COLS];
__device__ float g_QA[H * NN * 32];          // per-head q features [h][i][32]
__device__ float g_KB[H * NN * 32];          // per-head k features [h][j][32]
__device__ float g_vcombT[H * 40 * NN];      // per-head v (16 scalar + 24 point), [h][d][j]
__device__ float g_lp[NN * H * NN];          // logits [i][h][j]
__device__ float g_attn[NN * H * NN];        // normalized attn weights [i][h][j]
__device__ float g_res[NN * RES_COLS];

// ---------------------------------------------------------------------------
// cp.async helpers (.cg = L2-only, data is touch-once)
// ---------------------------------------------------------------------------
__device__ __forceinline__ void cp_async16(void* smem_dst, const void* gmem_src) {
    uint32_t dst = (uint32_t)__cvta_generic_to_shared(smem_dst);
    asm volatile("cp.async.cg.shared.global [%0], [%1], 16;" :: "r"(dst), "l"(gmem_src));
}
__device__ __forceinline__ void cp_commit() {
    asm volatile("cp.async.commit_group;");
}
template <int N>
__device__ __forceinline__ void cp_wait() {
    asm volatile("cp.async.wait_group %0;" :: "n"(N));
}

// Stage one contiguous 32j x 128d pair tile (16 KB) with cp.async; 256 threads.
__device__ __forceinline__ void stage_pair_tile(float* sbuf, const float* pairRow,
                                                int j0, int t)
{
    const float* src = pairRow + (size_t)j0 * PDIM;
    #pragma unroll
    for (int m = 0; m < 4; m++) {
        int idx = t + 256 * m;           // 0..1023 float4 slots
        cp_async16(&sbuf[4 * idx], src + 4 * idx);
    }
    cp_commit();
}

// ---------------------------------------------------------------------------
// Kernel 1: concat projection weights into [384 x 768]
// ---------------------------------------------------------------------------
__global__ void concat_w_kernel(const float* __restrict__ Wsq, const float* __restrict__ Wsk,
                                const float* __restrict__ Wsv, const float* __restrict__ Wpq,
                                const float* __restrict__ Wpk, const float* __restrict__ Wpv)
{
    int idx = blockIdx.x * blockDim.x + threadIdx.x;
    if (idx >= DIM * PROJ_COLS) return;
    int k = idx / PROJ_COLS;
    int c = idx - k * PROJ_COLS;
    float v;
    if (c < 128)       v = Wsq[k * 128 + c];
    else if (c < 256)  v = Wsk[k * 128 + (c - 128)];
    else if (c < 384)  v = Wsv[k * 128 + (c - 256)];
    else if (c < 480)  v = Wpq[k * 96 + (c - 384)];
    else if (c < 576)  v = Wpk[k * 96 + (c - 480)];
    else               v = Wpv[k * 192 + (c - 576)];
    g_Wcat[idx] = v;
}

// ---------------------------------------------------------------------------
// 64x64 tiled fp32 GEMM, 4x4 microtile, BK=16.  C (+)= A[M,K]*B[K,N].
// ---------------------------------------------------------------------------
__global__ __launch_bounds__(256) void gemm64_kernel(const float* __restrict__ A,
                                                     const float* __restrict__ B,
                                                     float* __restrict__ C,
                                                     int M, int N, int K,
                                                     int kChunk, int useAtomic)
{
    __shared__ float As[16][68];   // [k][m]
    __shared__ float Bs[16][68];   // [k][n]
    const int bm = blockIdx.y * 64;
    const int bn = blockIdx.x * 64;
    int k0 = blockIdx.z * kChunk;
    int k1 = k0 + kChunk; if (k1 > K) k1 = K;
    const int t  = threadIdx.x;
    const int tx = t & 15, ty = t >> 4;

    const int lm  = t >> 2;
    const int lk4 = (t & 3) * 4;
    const int lkb = t >> 4;
    const int lnb = (t & 15) * 4;

    float acc[4][4];
    #pragma unroll
    for (int r = 0; r < 4; r++)
        #pragma unroll
        for (int c = 0; c < 4; c++) acc[r][c] = 0.f;

    for (int kt = k0; kt < k1; kt += 16) {
        float4 a4 = *(const float4*)&A[(size_t)(bm + lm) * K + kt + lk4];
        float4 b4 = *(const float4*)&B[(size_t)(kt + lkb) * N + bn + lnb];
        __syncthreads();
        As[lk4 + 0][lm] = a4.x; As[lk4 + 1][lm] = a4.y;
        As[lk4 + 2][lm] = a4.z; As[lk4 + 3][lm] = a4.w;
        *(float4*)&Bs[lkb][lnb] = b4;
        __syncthreads();
        #pragma unroll
        for (int kk = 0; kk < 16; kk++) {
            float4 av = *(const float4*)&As[kk][ty * 4];
            float4 bv = *(const float4*)&Bs[kk][tx * 4];
            acc[0][0] += av.x * bv.x; acc[0][1] += av.x * bv.y; acc[0][2] += av.x * bv.z; acc[0][3] += av.x * bv.w;
            acc[1][0] += av.y * bv.x; acc[1][1] += av.y * bv.y; acc[1][2] += av.y * bv.z; acc[1][3] += av.y * bv.w;
            acc[2][0] += av.z * bv.x; acc[2][1] += av.z * bv.y; acc[2][2] += av.z * bv.z; acc[2][3] += av.z * bv.w;
            acc[3][0] += av.w * bv.x; acc[3][1] += av.w * bv.y; acc[3][2] += av.w * bv.z; acc[3][3] += av.w * bv.w;
        }
    }
    #pragma unroll
    for (int r = 0; r < 4; r++) {
        float* cp = &C[(size_t)(bm + ty * 4 + r) * N + bn + tx * 4];
        if (useAtomic) {
            atomicAdd(cp + 0, acc[r][0]); atomicAdd(cp + 1, acc[r][1]);
            atomicAdd(cp + 2, acc[r][2]); atomicAdd(cp + 3, acc[r][3]);
        } else {
            float4 v; v.x = acc[r][0]; v.y = acc[r][1]; v.z = acc[r][2]; v.w = acc[r][3];
            *(float4*)cp = v;
        }
    }
}

// ---------------------------------------------------------------------------
// Kernel 3: build per-head GEMM operand matrices.
// ---------------------------------------------------------------------------
__global__ void transform_kernel(const float* __restrict__ rot, const float* __restrict__ trans,
                                 const float* __restrict__ point_weights)
{
    int tid = blockIdx.x * blockDim.x + threadIdx.x;
    if (tid >= H * NN) return;
    int h = tid >> 9, n = tid & 511;
    float pwh = log1pf(__expf(point_weights[h]));
    float cP = -0.5f * pwh * kScalePoint;
    const float* R = rot + n * 9;
    const float t0 = trans[n * 3 + 0], t1 = trans[n * 3 + 1], t2 = trans[n * 3 + 2];
    const float* pr = g_proj + (size_t)n * PROJ_COLS;
    float* qa = g_QA + ((size_t)h * NN + n) * 32;
    float* kb = g_KB + ((size_t)h * NN + n) * 32;

    #pragma unroll
    for (int d = 0; d < 16; d++) {
        qa[d] = pr[h * 16 + d] * kScaleScalar;
        kb[d] = pr[128 + h * 16 + d];
    }
    float qq = 0.f, kk = 0.f;
    #pragma unroll
    for (int pd = 0; pd < 4; pd++) {
        const float* q = pr + 384 + h * 12 + pd * 3;
        float g0 = q[0] * R[0] + q[1] * R[3] + q[2] * R[6] + t0;
        float g1 = q[0] * R[1] + q[1] * R[4] + q[2] * R[7] + t1;
        float g2 = q[0] * R[2] + q[1] * R[5] + q[2] * R[8] + t2;
        qa[16 + pd * 3 + 0] = -2.f * cP * g0;
        qa[16 + pd * 3 + 1] = -2.f * cP * g1;
        qa[16 + pd * 3 + 2] = -2.f * cP * g2;
        qq += g0 * g0 + g1 * g1 + g2 * g2;
        const float* k = pr + 480 + h * 12 + pd * 3;
        float f0 = k[0] * R[0] + k[1] * R[3] + k[2] * R[6] + t0;
        float f1 = k[0] * R[1] + k[1] * R[4] + k[2] * R[7] + t1;
        float f2 = k[0] * R[2] + k[1] * R[5] + k[2] * R[8] + t2;
        kb[16 + pd * 3 + 0] = f0;
        kb[16 + pd * 3 + 1] = f1;
        kb[16 + pd * 3 + 2] = f2;
        kk += f0 * f0 + f1 * f1 + f2 * f2;
    }
    qa[28] = cP * qq; qa[29] = 1.f; qa[30] = 0.f; qa[31] = 0.f;
    kb[28] = 1.f; kb[29] = cP * kk; kb[30] = 0.f; kb[31] = 0.f;

    #pragma unroll
    for (int d = 0; d < 16; d++)
        g_vcombT[((size_t)h * 40 + d) * NN + n] = pr[256 + h * 16 + d];
    #pragma unroll
    for (int pv = 0; pv < 8; pv++) {
        const float* v = pr + 576 + h * 24 + pv * 3;
        float g0 = v[0] * R[0] + v[1] * R[3] + v[2] * R[6] + t0;
        float g1 = v[0] * R[1] + v[1] * R[4] + v[2] * R[7] + t1;
        float g2 = v[0] * R[2] + v[1] * R[5] + v[2] * R[8] + t2;
        g_vcombT[((size_t)h * 40 + 16 + pv * 3 + 0) * NN + n] = g0;
        g_vcombT[((size_t)h * 40 + 16 + pv * 3 + 1) * NN + n] = g1;
        g_vcombT[((size_t)h * 40 + 16 + pv * 3 + 2) * NN + n] = g2;
    }
}

// ---------------------------------------------------------------------------
// Kernel 4: QK logit GEMM.  g_lp[i][h][j] = QA[h][i] . KB[h][j]
// Grid (8 jt, 8 it, 8 h); block computes 64i x 64j, K=32.
// ---------------------------------------------------------------------------
__global__ __launch_bounds__(256) void logit_gemm_kernel()
{
    const int h = blockIdx.z;
    const int i0 = blockIdx.y * 64;
    const int j0 = blockIdx.x * 64;
    __shared__ float sQ[32][68];   // [k][i]
    __shared__ float sK[32][68];   // [k][j]
    const int t = threadIdx.x, tx = t & 15, ty = t >> 4;

    #pragma unroll
    for (int m = 0; m < 8; m++) {
        int idx = t + 256 * m;
        int row = idx >> 5, k = idx & 31;
        sQ[k][row] = g_QA[((size_t)h * NN + i0 + row) * 32 + k];
        sK[k][row] = g_KB[((size_t)h * NN + j0 + row) * 32 + k];
    }
    __syncthreads();

    float acc[4][4];
    #pragma unroll
    for (int r = 0; r < 4; r++)
        #pragma unroll
        for (int c = 0; c < 4; c++) acc[r][c] = 0.f;

    #pragma unroll
    for (int kk = 0; kk < 32; kk++) {
        float4 a = *(const float4*)&sQ[kk][ty * 4];
        float4 b = *(const float4*)&sK[kk][tx * 4];
        acc[0][0] += a.x * b.x; acc[0][1] += a.x * b.y; acc[0][2] += a.x * b.z; acc[0][3] += a.x * b.w;
        acc[1][0] += a.y * b.x; acc[1][1] += a.y * b.y; acc[1][2] += a.y * b.z; acc[1][3] += a.y * b.w;
        acc[2][0] += a.z * b.x; acc[2][1] += a.z * b.y; acc[2][2] += a.z * b.z; acc[2][3] += a.z * b.w;
        acc[3][0] += a.w * b.x; acc[3][1] += a.w * b.y; acc[3][2] += a.w * b.z; acc[3][3] += a.w * b.w;
    }
    #pragma unroll
    for (int r = 0; r < 4; r++) {
        float4 v;
        v.x = acc[r][0]; v.y = acc[r][1]; v.z = acc[r][2]; v.w = acc[r][3];
        *(float4*)&g_lp[(((size_t)i0 + ty * 4 + r) * H + h) * NN + j0 + tx * 4] = v;
    }
}

// ---------------------------------------------------------------------------
// Kernel 5: pair-bias logits, j-split 4-way.  Grid (4 jq, 512 i).
//   g_lp[i][h][j] += (pair[i,j,:]@Wpair[:,h] + bpair[h]) * scalePair
// Block streams 128 j rows (4 tiles, cp.async double-buffer, 32 KB smem).
// ---------------------------------------------------------------------------
__global__ __launch_bounds__(256) void pair_bias_kernel(const float* __restrict__ pairw,
                                                        const float* __restrict__ Wpair,
                                                        const float* __restrict__ bpair)
{
    const int i = blockIdx.y;
    const int jbase = blockIdx.x * 128;
    const int t = threadIdx.x;
    const int w = t >> 5, lane = t & 31;
    const int hp = lane >> 3;            // head pair 0..3 -> heads 2hp, 2hp+1
    const int s  = lane & 7;             // d-slice 0..7

    __shared__ __align__(16) float sP[2][32 * 128];   // 2 x 16 KB

    const int h0 = 2 * hp, h1 = 2 * hp + 1;
    float4 W0[4], W1[4];
    #pragma unroll
    for (int k = 0; k < 4; k++) {
        int d0 = 4 * (s + 8 * k);
        W0[k].x = Wpair[(d0 + 0) * 8 + h0]; W1[k].x = Wpair[(d0 + 0) * 8 + h1];
        W0[k].y = Wpair[(d0 + 1) * 8 + h0]; W1[k].y = Wpair[(d0 + 1) * 8 + h1];
        W0[k].z = Wpair[(d0 + 2) * 8 + h0]; W1[k].z = Wpair[(d0 + 2) * 8 + h1];
        W0[k].w = Wpair[(d0 + 3) * 8 + h0]; W1[k].w = Wpair[(d0 + 3) * 8 + h1];
    }
    const float bb0 = bpair[h0] * kScalePair;
    const float bb1 = bpair[h1] * kScalePair;
    const float* pairRow = pairw + (size_t)i * NN * PDIM;

    stage_pair_tile(sP[0], pairRow, jbase, t);
    for (int jt = 0; jt < 128; jt += 32) {
        int b = (jt >> 5) & 1;
        if (jt + 32 < 128) { stage_pair_tile(sP[b ^ 1], pairRow, jbase + jt + 32, t); cp_wait<1>(); }
        else               { cp_wait<0>(); }
        __syncthreads();
        #pragma unroll
        for (int u = 0; u < 4; u++) {
            int jj = (w << 2) + u;
            const float* row = &sP[b][jj * 128];
            float a0 = 0.f, a1 = 0.f;
            #pragma unroll
            for (int k = 0; k < 4; k++) {
                float4 p = *(const float4*)&row[4 * (s + 8 * k)];
                a0 += p.x * W0[k].x + p.y * W0[k].y + p.z * W0[k].z + p.w * W0[k].w;
                a1 += p.x * W1[k].x + p.y * W1[k].y + p.z * W1[k].z + p.w * W1[k].w;
            }
            #pragma unroll
            for (int o = 1; o < 8; o <<= 1) {
                a0 += __shfl_xor_sync(0xffffffffu, a0, o);
                a1 += __shfl_xor_sync(0xffffffffu, a1, o);
            }
            if (s == 0) {
                int j = jbase + jt + jj;
                g_lp[((size_t)i * H + h0) * NN + j] += a0 * kScalePair + bb0;
                g_lp[((size_t)i * H + h1) * NN + j] += a1 * kScalePair + bb1;
            }
        }
        __syncthreads();
    }
}

// ---------------------------------------------------------------------------
// Kernel 6: softmax.  Block per i, warp per head.  g_lp -> g_attn.
// ---------------------------------------------------------------------------
__global__ __launch_bounds__(256) void softmax_kernel()
{
    const int i = blockIdx.x;
    const int w = threadIdx.x >> 5, lane = threadIdx.x & 31;
    const float* src = g_lp + ((size_t)i * H + w) * NN;
    float* dst = g_attn + ((size_t)i * H + w) * NN;

    float4 v[4];
    #pragma unroll
    for (int q = 0; q < 4; q++) v[q] = *(const float4*)&src[q * 128 + lane * 4];

    float m = -1e30f;
    #pragma unroll
    for (int q = 0; q < 4; q++)
        m = fmaxf(m, fmaxf(fmaxf(v[q].x, v[q].y), fmaxf(v[q].z, v[q].w)));
    #pragma unroll
    for (int o = 16; o; o >>= 1) m = fmaxf(m, __shfl_xor_sync(0xffffffffu, m, o));

    float sum = 0.f;
    #pragma unroll
    for (int q = 0; q < 4; q++) {
        v[q].x = __expf(v[q].x - m); v[q].y = __expf(v[q].y - m);
        v[q].z = __expf(v[q].z - m); v[q].w = __expf(v[q].w - m);
        sum += v[q].x + v[q].y + v[q].z + v[q].w;
    }
    #pragma unroll
    for (int o = 16; o; o >>= 1) sum += __shfl_xor_sync(0xffffffffu, sum, o);
    float inv = 1.f / sum;
    #pragma unroll
    for (int q = 0; q < 4; q++) {
        v[q].x *= inv; v[q].y *= inv; v[q].z *= inv; v[q].w *= inv;
        *(float4*)&dst[q * 128 + lane * 4] = v[q];
    }
}

// ---------------------------------------------------------------------------
// Kernel 7: AV GEMM + epilogue.  Grid (16 it, 8 h); block: C[32 i][40 d], K=512.
// ---------------------------------------------------------------------------
__global__ __launch_bounds__(256) void av_kernel(const float* __restrict__ rot,
                                                 const float* __restrict__ trans)
{
    const int h = blockIdx.y;
    const int i0 = blockIdx.x * 32;
    const int t = threadIdx.x;
    const int ti = t >> 3, tg = t & 7;   // 32 i-rows x 8 d-groups of 5

    __shared__ float sA[32][33];
    __shared__ float sV[40][33];
    __shared__ float sC[32][41];

    float acc[5];
    #pragma unroll
    for (int q = 0; q < 5; q++) acc[q] = 0.f;

    for (int jt = 0; jt < NN; jt += 32) {
        __syncthreads();
        #pragma unroll
        for (int m = 0; m < 4; m++) {
            int idx = t + 256 * m;
            int il = idx >> 5, jj = idx & 31;
            sA[il][jj] = g_attn[(((size_t)i0 + il) * H + h) * NN + jt + jj];
        }
        #pragma unroll
        for (int m = 0; m < 5; m++) {
            int idx = t + 256 * m;
            int d = idx >> 5, jj = idx & 31;
            sV[d][jj] = g_vcombT[((size_t)h * 40 + d) * NN + jt + jj];
        }
        __syncthreads();
        #pragma unroll 4
        for (int jj = 0; jj < 32; jj++) {
            float a = sA[ti][jj];
            #pragma unroll
            for (int q = 0; q < 5; q++) acc[q] += a * sV[tg * 5 + q][jj];
        }
    }
    __syncthreads();
    #pragma unroll
    for (int q = 0; q < 5; q++) sC[ti][tg * 5 + q] = acc[q];
    __syncthreads();

    // scalar outputs: 32 x 16
    #pragma unroll
    for (int m = 0; m < 2; m++) {
        int idx = t + 256 * m;
        int il = idx >> 4, d = idx & 15;
        g_res[((size_t)i0 + il) * RES_COLS + h * 16 + d] = sC[il][d];
    }
    // point outputs: 32 x 8 -> back-transform + norm
    {
        int il = t >> 3, pv = t & 7;
        int i = i0 + il;
        float g0 = sC[il][16 + pv * 3 + 0] - trans[i * 3 + 0];
        float g1 = sC[il][16 + pv * 3 + 1] - trans[i * 3 + 1];
        float g2 = sC[il][16 + pv * 3 + 2] - trans[i * 3 + 2];
        const float* R = rot + i * 9;
        float n2 = EPSV;
        #pragma unroll
        for (int r = 0; r < 3; r++) {
            float lr = g0 * R[r * 3 + 0] + g1 * R[r * 3 + 1] + g2 * R[r * 3 + 2];
            g_res[(size_t)i * RES_COLS + 128 + h * 24 + pv * 3 + r] = lr;
            n2 += lr * lr;
        }
        g_res[(size_t)i * RES_COLS + 320 + h * 8 + pv] = sqrtf(n2);
    }
}

// ---------------------------------------------------------------------------
// Kernel 8: zero the res_pair region of g_res (accumulated atomically).
// ---------------------------------------------------------------------------
__global__ void zero_pair_kernel()
{
    int idx = blockIdx.x * blockDim.x + threadIdx.x;   // 512*256 float4
    if (idx >= NN * 256) return;
    int i = idx >> 8, r4 = idx & 255;
    *(float4*)&g_res[(size_t)i * RES_COLS + 384 + 4 * r4] = make_float4(0.f, 0.f, 0.f, 0.f);
}

// ---------------------------------------------------------------------------
// Kernel 9: res_pair, j-split 4-way.  Grid (4 jq, 512 i).
//   g_res[i][384 + h*128 + d] += sum_{j in quarter} attn[i,h,j] * pair[i,j,d]
// Warp = (head-group hg = w&1, row-eighth jh = w>>1); smem partial reduce;
// atomicAdd combine across the 4 j-quarter blocks.
// ---------------------------------------------------------------------------
__global__ __launch_bounds__(256) void res_pair_kernel(const float* __restrict__ pairw)
{
    const int i = blockIdx.y;
    const int jbase = blockIdx.x * 128;
    const int t = threadIdx.x;
    const int w = t >> 5, lane = t & 31;
    const int hg = w & 1;                 // heads 4hg .. 4hg+3
    const int jh = w >> 1;                // rows [8jh, 8jh+8) within tile

    __shared__ __align__(16) float sP[2][32 * 128];   // 32 KB
    __shared__ float sW[H * 128];                     // attn [h][j-local], 4 KB
    __shared__ float4 sPart[8][4][32];                // 16 KB partials

    {   // load this quarter's attn weights: thread t -> (h = t>>5, j4 = t&31)
        const float* src = g_attn + (size_t)i * H * NN + jbase;
        int hh = t >> 5, j4 = t & 31;
        *(float4*)&sW[hh * 128 + 4 * j4] = *(const float4*)&src[(size_t)hh * NN + 4 * j4];
    }
    const float* pairRow = pairw + (size_t)i * NN * PDIM;
    const float* w0 = &sW[(4 * hg + 0) * 128];
    const float* w1 = &sW[(4 * hg + 1) * 128];
    const float* w2 = &sW[(4 * hg + 2) * 128];
    const float* w3 = &sW[(4 * hg + 3) * 128];

    float4 acc0 = make_float4(0.f, 0.f, 0.f, 0.f);
    float4 acc1 = acc0, acc2 = acc0, acc3 = acc0;

    stage_pair_tile(sP[0], pairRow, jbase, t);
    for (int jt = 0; jt < 128; jt += 32) {
        int b = (jt >> 5) & 1;
        if (jt + 32 < 128) { stage_pair_tile(sP[b ^ 1], pairRow, jbase + jt + 32, t); cp_wait<1>(); }
        else               { cp_wait<0>(); }
        __syncthreads();
        const float* base = &sP[b][(8 * jh) * 128 + 4 * lane];
        #pragma unroll
        for (int r = 0; r < 8; r++) {
            int jl = jt + 8 * jh + r;
            float4 p = *(const float4*)&base[r * 128];
            float g0 = w0[jl], g1 = w1[jl], g2 = w2[jl], g3 = w3[jl];
            acc0.x += g0 * p.x; acc0.y += g0 * p.y; acc0.z += g0 * p.z; acc0.w += g0 * p.w;
            acc1.x += g1 * p.x; acc1.y += g1 * p.y; acc1.z += g1 * p.z; acc1.w += g1 * p.w;
            acc2.x += g2 * p.x; acc2.y += g2 * p.y; acc2.z += g2 * p.z; acc2.w += g2 * p.w;
            acc3.x += g3 * p.x; acc3.y += g3 * p.y; acc3.z += g3 * p.z; acc3.w += g3 * p.w;
        }
        __syncthreads();
    }

    sPart[w][0][lane] = acc0;
    sPart[w][1][lane] = acc1;
    sPart[w][2][lane] = acc2;
    sPart[w][3][lane] = acc3;
    __syncthreads();

    {   // thread t = h*32 + d4: sum 4 row-eighth partials, atomic combine
        int h = t >> 5, d4 = t & 31;
        int hgq = h >> 2, hh = h & 3;
        float4 r = make_float4(0.f, 0.f, 0.f, 0.f);
        #pragma unroll
        for (int q = 0; q < 4; q++) {
            float4 p = sPart[2 * q + hgq][hh][d4];
            r.x += p.x; r.y += p.y; r.z += p.z; r.w += p.w;
        }
        float* dst = &g_res[(size_t)i * RES_COLS + 384 + h * 128 + 4 * d4];
        atomicAdd(dst + 0, r.x); atomicAdd(dst + 1, r.y);
        atomicAdd(dst + 2, r.z); atomicAdd(dst + 3, r.w);
    }
}

// ---------------------------------------------------------------------------
// Kernel 10: init output with bias (for split-K atomic GEMM)
// ---------------------------------------------------------------------------
__global__ void init_out_kernel(float* __restrict__ out, const float* __restrict__ bout)
{
    int idx = blockIdx.x * blockDim.x + threadIdx.x;
    if (idx < NN * DIM) out[idx] = bout[idx % DIM];
}

// ---------------------------------------------------------------------------
extern "C" void kernel_launch(void* const* d_in, const int* in_sizes, int n_in,
                              void* d_out, int out_size)
{
    const float* x      = (const float*)d_in[0];
    const float* pairw  = (const float*)d_in[1];
    const float* rot    = (const float*)d_in[2];
    const float* trans  = (const float*)d_in[3];
    const float* Wsq    = (const float*)d_in[4];
    const float* Wsk    = (const float*)d_in[5];
    const float* Wsv    = (const float*)d_in[6];
    const float* Wpq    = (const float*)d_in[7];
    const float* Wpk    = (const float*)d_in[8];
    const float* Wpv    = (const float*)d_in[9];
    const float* pw     = (const float*)d_in[10];
    const float* Wpair  = (const float*)d_in[11];
    const float* bpair  = (const float*)d_in[12];
    const float* Wout   = (const float*)d_in[13];
    const float* bout   = (const float*)d_in[14];
    float* out = (float*)d_out;

    float *pWcat, *pProj, *pRes;
    cudaGetSymbolAddress((void**)&pWcat, g_Wcat);
    cudaGetSymbolAddress((void**)&pProj, g_proj);
    cudaGetSymbolAddress((void**)&pRes,  g_res);

    // 1. concat weights
    concat_w_kernel<<<(DIM * PROJ_COLS + 255) / 256, 256>>>(Wsq, Wsk, Wsv, Wpq, Wpk, Wpv);

    // 2. projections: proj[512,768] = x @ Wcat
    gemm64_kernel<<<dim3(PROJ_COLS / 64, NN / 64), 256>>>(x, pWcat, pProj,
                                                          NN, PROJ_COLS, DIM, DIM, 0);

    // 3. build QA/KB/vcombT
    transform_kernel<<<(H * NN) / 256, 256>>>(rot, trans, pw);

    // 4. QK logits (scalar + point) via K=32 GEMM -> g_lp
    logit_gemm_kernel<<<dim3(8, 8, 8), 256>>>();

    // 5. pair-bias logits, 4-way j-split (first pairwise stream)
    pair_bias_kernel<<<dim3(4, NN), 256>>>(pairw, Wpair, bpair);

    // 6. softmax -> g_attn
    softmax_kernel<<<NN, 256>>>();

    // 7. AV GEMM (res_scalar + res_point + norms)
    av_kernel<<<dim3(16, 8), 256>>>(rot, trans);

    // 8. zero res_pair region, then res_pair 4-way j-split (second stream)
    zero_pair_kernel<<<(NN * 256 + 255) / 256, 256>>>();
    res_pair_kernel<<<dim3(4, NN), 256>>>(pairw);

    // 9-10. out = res @ Wout + bout   (split-K=8, atomic)
    init_out_kernel<<<(NN * DIM + 255) / 256, 256>>>(out, bout);
    gemm64_kernel<<<dim3(DIM / 64, NN / 64, 8), 256>>>(pRes, Wout, out,
                                                       NN, DIM, RES_COLS, 176, 1);
}

// round 12
// speedup vs baseline: 1.2175x; 1.2175x over previous
#include <cuda_runtime.h>
#include <cuda_bf16.h>
#include <cstdint>
#include <math.h>

// Problem constants
#define NN 512
#define DIM 384
#define PDIM 128
#define H 8
#define SK 16
#define SV 16
#define PK 4
#define PV 8
#define PROJ_COLS 768           // 128+128+128+96+96+192
#define RES_COLS 1408           // 128 + 192 + 64 + 1024
#define EPSV 1e-8f
#define LP 516                  // sL pitch (floats)

__device__ __constant__ float kScaleScalar = 0.14433756729740643f;  // (3*16)^-0.5
__device__ __constant__ float kScalePoint  = 0.13608276348795434f;  // (3*4*4.5)^-0.5
__device__ __constant__ float kScalePair   = 0.57735026918962576f;  // 3^-0.5

// Scratch (allocation-free contract: __device__ globals)
__device__ float g_Wcat[DIM * PROJ_COLS];
__device__ float g_proj[NN * PROJ_COLS];
__device__ float g_QA[H * NN * 32];          // per-head q features [h][i][32]
__device__ float g_KB[H * NN * 32];          // per-head k features [h][j][32]
__device__ float g_vcombT[H * 40 * NN];      // per-head v (16 scalar + 24 point), [h][d][j]
__device__ float g_lp[NN * H * NN];          // QK logits [i][h][j]
__device__ float g_attn[NN * H * NN];        // normalized attn weights [i][h][j]
__device__ float g_res[NN * RES_COLS];

// ---------------------------------------------------------------------------
// packed f32x2 helpers (2 fp32 MACs per instruction; exact fp32 semantics)
// ---------------------------------------------------------------------------
__device__ __forceinline__ void ffma2(unsigned long long& acc,
                                      unsigned long long a, unsigned long long b) {
    asm("fma.rn.f32x2 %0, %1, %2, %0;" : "+l"(acc) : "l"(a), "l"(b));
}
__device__ __forceinline__ unsigned long long pack2(float lo, float hi) {
    unsigned long long r;
    asm("mov.b64 %0, {%1, %2};" : "=l"(r) : "f"(lo), "f"(hi));
    return r;
}
__device__ __forceinline__ float hadd2(unsigned long long v) {
    float lo, hi;
    asm("mov.b64 {%0, %1}, %2;" : "=f"(lo), "=f"(hi) : "l"(v));
    return lo + hi;
}
union F4U2 { float4 f; unsigned long long u[2]; };

// ---------------------------------------------------------------------------
// cp.async helpers (.cg = L2-only, data is touch-once)
// ---------------------------------------------------------------------------
__device__ __forceinline__ void cp_async16(void* smem_dst, const void* gmem_src) {
    uint32_t dst = (uint32_t)__cvta_generic_to_shared(smem_dst);
    asm volatile("cp.async.cg.shared.global [%0], [%1], 16;" :: "r"(dst), "l"(gmem_src));
}
__device__ __forceinline__ void cp_commit() {
    asm volatile("cp.async.commit_group;");
}
template <int N>
__device__ __forceinline__ void cp_wait() {
    asm volatile("cp.async.wait_group %0;" :: "n"(N));
}

// Stage one contiguous 32j x 128d pair tile (16 KB) with cp.async; 256 threads.
__device__ __forceinline__ void stage_pair_tile(float* sbuf, const float* pairRow,
                                                int j0, int t)
{
    const float* src = pairRow + (size_t)j0 * PDIM;
    #pragma unroll
    for (int m = 0; m < 4; m++) {
        int idx = t + 256 * m;           // 0..1023 float4 slots
        cp_async16(&sbuf[4 * idx], src + 4 * idx);
    }
    cp_commit();
}

// ---------------------------------------------------------------------------
// Kernel 1: concat projection weights into [384 x 768]
// ---------------------------------------------------------------------------
__global__ void concat_w_kernel(const float* __restrict__ Wsq, const float* __restrict__ Wsk,
                                const float* __restrict__ Wsv, const float* __restrict__ Wpq,
                                const float* __restrict__ Wpk, const float* __restrict__ Wpv)
{
    int idx = blockIdx.x * blockDim.x + threadIdx.x;
    if (idx >= DIM * PROJ_COLS) return;
    int k = idx / PROJ_COLS;
    int c = idx - k * PROJ_COLS;
    float v;
    if (c < 128)       v = Wsq[k * 128 + c];
    else if (c < 256)  v = Wsk[k * 128 + (c - 128)];
    else if (c < 384)  v = Wsv[k * 128 + (c - 256)];
    else if (c < 480)  v = Wpq[k * 96 + (c - 384)];
    else if (c < 576)  v = Wpk[k * 96 + (c - 480)];
    else               v = Wpv[k * 192 + (c - 576)];
    g_Wcat[idx] = v;
}

// ---------------------------------------------------------------------------
// 64x64 tiled fp32 GEMM, 4x4 microtile, BK=16, f32x2 packed inner loop.
// ---------------------------------------------------------------------------
__global__ __launch_bounds__(256) void gemm64_kernel(const float* __restrict__ A,
                                                     const float* __restrict__ B,
                                                     float* __restrict__ C,
                                                     int M, int N, int K,
                                                     int kChunk, int useAtomic)
{
    __shared__ float As[16][68];   // [k][m]
    __shared__ float Bs[16][68];   // [k][n]
    const int bm = blockIdx.y * 64;
    const int bn = blockIdx.x * 64;
    int k0 = blockIdx.z * kChunk;
    int k1 = k0 + kChunk; if (k1 > K) k1 = K;
    const int t  = threadIdx.x;
    const int tx = t & 15, ty = t >> 4;

    const int lm  = t >> 2;
    const int lk4 = (t & 3) * 4;
    const int lkb = t >> 4;
    const int lnb = (t & 15) * 4;

    unsigned long long accU[4][2];
    #pragma unroll
    for (int r = 0; r < 4; r++) { accU[r][0] = 0ull; accU[r][1] = 0ull; }

    for (int kt = k0; kt < k1; kt += 16) {
        float4 a4 = *(const float4*)&A[(size_t)(bm + lm) * K + kt + lk4];
        float4 b4 = *(const float4*)&B[(size_t)(kt + lkb) * N + bn + lnb];
        __syncthreads();
        As[lk4 + 0][lm] = a4.x; As[lk4 + 1][lm] = a4.y;
        As[lk4 + 2][lm] = a4.z; As[lk4 + 3][lm] = a4.w;
        *(float4*)&Bs[lkb][lnb] = b4;
        __syncthreads();
        #pragma unroll
        for (int kk = 0; kk < 16; kk++) {
            float4 av = *(const float4*)&As[kk][ty * 4];
            F4U2 bv; bv.f = *(const float4*)&Bs[kk][tx * 4];
            unsigned long long ax = pack2(av.x, av.x);
            unsigned long long ay = pack2(av.y, av.y);
            unsigned long long az = pack2(av.z, av.z);
            unsigned long long aw = pack2(av.w, av.w);
            ffma2(accU[0][0], ax, bv.u[0]); ffma2(accU[0][1], ax, bv.u[1]);
            ffma2(accU[1][0], ay, bv.u[0]); ffma2(accU[1][1], ay, bv.u[1]);
            ffma2(accU[2][0], az, bv.u[0]); ffma2(accU[2][1], az, bv.u[1]);
            ffma2(accU[3][0], aw, bv.u[0]); ffma2(accU[3][1], aw, bv.u[1]);
        }
    }
    #pragma unroll
    for (int r = 0; r < 4; r++) {
        F4U2 v; v.u[0] = accU[r][0]; v.u[1] = accU[r][1];
        float* cp = &C[(size_t)(bm + ty * 4 + r) * N + bn + tx * 4];
        if (useAtomic) {
            atomicAdd(cp + 0, v.f.x); atomicAdd(cp + 1, v.f.y);
            atomicAdd(cp + 2, v.f.z); atomicAdd(cp + 3, v.f.w);
        } else {
            *(float4*)cp = v.f;
        }
    }
}

// ---------------------------------------------------------------------------
// Kernel 3: build per-head GEMM operand matrices.
// ---------------------------------------------------------------------------
__global__ void transform_kernel(const float* __restrict__ rot, const float* __restrict__ trans,
                                 const float* __restrict__ point_weights)
{
    int tid = blockIdx.x * blockDim.x + threadIdx.x;
    if (tid >= H * NN) return;
    int h = tid >> 9, n = tid & 511;
    float pwh = log1pf(__expf(point_weights[h]));
    float cP = -0.5f * pwh * kScalePoint;
    const float* R = rot + n * 9;
    const float t0 = trans[n * 3 + 0], t1 = trans[n * 3 + 1], t2 = trans[n * 3 + 2];
    const float* pr = g_proj + (size_t)n * PROJ_COLS;
    float* qa = g_QA + ((size_t)h * NN + n) * 32;
    float* kb = g_KB + ((size_t)h * NN + n) * 32;

    #pragma unroll
    for (int d = 0; d < 16; d++) {
        qa[d] = pr[h * 16 + d] * kScaleScalar;
        kb[d] = pr[128 + h * 16 + d];
    }
    float qq = 0.f, kk = 0.f;
    #pragma unroll
    for (int pd = 0; pd < 4; pd++) {
        const float* q = pr + 384 + h * 12 + pd * 3;
        float g0 = q[0] * R[0] + q[1] * R[3] + q[2] * R[6] + t0;
        float g1 = q[0] * R[1] + q[1] * R[4] + q[2] * R[7] + t1;
        float g2 = q[0] * R[2] + q[1] * R[5] + q[2] * R[8] + t2;
        qa[16 + pd * 3 + 0] = -2.f * cP * g0;
        qa[16 + pd * 3 + 1] = -2.f * cP * g1;
        qa[16 + pd * 3 + 2] = -2.f * cP * g2;
        qq += g0 * g0 + g1 * g1 + g2 * g2;
        const float* k = pr + 480 + h * 12 + pd * 3;
        float f0 = k[0] * R[0] + k[1] * R[3] + k[2] * R[6] + t0;
        float f1 = k[0] * R[1] + k[1] * R[4] + k[2] * R[7] + t1;
        float f2 = k[0] * R[2] + k[1] * R[5] + k[2] * R[8] + t2;
        kb[16 + pd * 3 + 0] = f0;
        kb[16 + pd * 3 + 1] = f1;
        kb[16 + pd * 3 + 2] = f2;
        kk += f0 * f0 + f1 * f1 + f2 * f2;
    }
    qa[28] = cP * qq; qa[29] = 1.f; qa[30] = 0.f; qa[31] = 0.f;
    kb[28] = 1.f; kb[29] = cP * kk; kb[30] = 0.f; kb[31] = 0.f;

    #pragma unroll
    for (int d = 0; d < 16; d++)
        g_vcombT[((size_t)h * 40 + d) * NN + n] = pr[256 + h * 16 + d];
    #pragma unroll
    for (int pv = 0; pv < 8; pv++) {
        const float* v = pr + 576 + h * 24 + pv * 3;
        float g0 = v[0] * R[0] + v[1] * R[3] + v[2] * R[6] + t0;
        float g1 = v[0] * R[1] + v[1] * R[4] + v[2] * R[7] + t1;
        float g2 = v[0] * R[2] + v[1] * R[5] + v[2] * R[8] + t2;
        g_vcombT[((size_t)h * 40 + 16 + pv * 3 + 0) * NN + n] = g0;
        g_vcombT[((size_t)h * 40 + 16 + pv * 3 + 1) * NN + n] = g1;
        g_vcombT[((size_t)h * 40 + 16 + pv * 3 + 2) * NN + n] = g2;
    }
}

// ---------------------------------------------------------------------------
// Kernel 4: QK logit GEMM.  g_lp[i][h][j] = QA[h][i] . KB[h][j]
// Grid (8 jt, 8 it, 8 h); 64i x 64j, K=32, f32x2 packed.
// ---------------------------------------------------------------------------
__global__ __launch_bounds__(256) void logit_gemm_kernel()
{
    const int h = blockIdx.z;
    const int i0 = blockIdx.y * 64;
    const int j0 = blockIdx.x * 64;
    __shared__ float sQ[32][68];   // [k][i]
    __shared__ float sK[32][68];   // [k][j]
    const int t = threadIdx.x, tx = t & 15, ty = t >> 4;

    #pragma unroll
    for (int m = 0; m < 8; m++) {
        int idx = t + 256 * m;
        int row = idx >> 5, k = idx & 31;
        sQ[k][row] = g_QA[((size_t)h * NN + i0 + row) * 32 + k];
        sK[k][row] = g_KB[((size_t)h * NN + j0 + row) * 32 + k];
    }
    __syncthreads();

    unsigned long long accU[4][2];
    #pragma unroll
    for (int r = 0; r < 4; r++) { accU[r][0] = 0ull; accU[r][1] = 0ull; }

    #pragma unroll
    for (int kk = 0; kk < 32; kk++) {
        float4 a = *(const float4*)&sQ[kk][ty * 4];
        F4U2 b; b.f = *(const float4*)&sK[kk][tx * 4];
        unsigned long long ax = pack2(a.x, a.x);
        unsigned long long ay = pack2(a.y, a.y);
        unsigned long long az = pack2(a.z, a.z);
        unsigned long long aw = pack2(a.w, a.w);
        ffma2(accU[0][0], ax, b.u[0]); ffma2(accU[0][1], ax, b.u[1]);
        ffma2(accU[1][0], ay, b.u[0]); ffma2(accU[1][1], ay, b.u[1]);
        ffma2(accU[2][0], az, b.u[0]); ffma2(accU[2][1], az, b.u[1]);
        ffma2(accU[3][0], aw, b.u[0]); ffma2(accU[3][1], aw, b.u[1]);
    }
    #pragma unroll
    for (int r = 0; r < 4; r++) {
        F4U2 v; v.u[0] = accU[r][0]; v.u[1] = accU[r][1];
        *(float4*)&g_lp[(((size_t)i0 + ty * 4 + r) * H + h) * NN + j0 + tx * 4] = v.f;
    }
}

// ---------------------------------------------------------------------------
// Kernel 5: pair-bias logits + softmax (fused).  Block per i.
//   preload QK logits -> stream pairwise (cp.async double-buffer),
//   head-paired lanes, f32x2 packed contraction -> softmax -> g_attn.
// ---------------------------------------------------------------------------
__global__ __launch_bounds__(256) void pair_logits_sm_kernel(const float* __restrict__ pairw,
                                                             const float* __restrict__ Wpair,
                                                             const float* __restrict__ bpair)
{
    const int i = blockIdx.x;
    const int t = threadIdx.x;
    const int w = t >> 5, lane = t & 31;
    const int hp = lane >> 3;            // head pair 0..3 -> heads 2hp, 2hp+1
    const int s  = lane & 7;             // d-slice 0..7

    __shared__ __align__(16) float sP[2][32 * 128];   // 2 x 16 KB tiles
    __shared__ float sL[H * LP];                      // logits -> weights

    const int h0 = 2 * hp, h1 = 2 * hp + 1;
    unsigned long long W0p[8], W1p[8];
    #pragma unroll
    for (int k = 0; k < 4; k++) {
        int d0 = 4 * (s + 8 * k);
        W0p[2 * k + 0] = pack2(Wpair[(d0 + 0) * 8 + h0], Wpair[(d0 + 1) * 8 + h0]);
        W0p[2 * k + 1] = pack2(Wpair[(d0 + 2) * 8 + h0], Wpair[(d0 + 3) * 8 + h0]);
        W1p[2 * k + 0] = pack2(Wpair[(d0 + 0) * 8 + h1], Wpair[(d0 + 1) * 8 + h1]);
        W1p[2 * k + 1] = pack2(Wpair[(d0 + 2) * 8 + h1], Wpair[(d0 + 3) * 8 + h1]);
    }
    const float bb0 = bpair[h0] * kScalePair;
    const float bb1 = bpair[h1] * kScalePair;
    const float* pairRow = pairw + (size_t)i * NN * PDIM;

    // preload QK logits into sL
    {
        const float* src = g_lp + (size_t)i * H * NN;
        #pragma unroll
        for (int m = 0; m < 4; m++) {
            int idx = t + 256 * m;
            int hh = idx >> 7, j4 = idx & 127;
            *(float4*)&sL[hh * LP + 4 * j4] = *(const float4*)&src[4 * idx];
        }
    }

    stage_pair_tile(sP[0], pairRow, 0, t);
    __syncthreads();                       // sL preload visible before +=
    for (int jt = 0; jt < NN; jt += 32) {
        int b = (jt >> 5) & 1;
        if (jt + 32 < NN) { stage_pair_tile(sP[b ^ 1], pairRow, jt + 32, t); cp_wait<1>(); }
        else              { cp_wait<0>(); }
        __syncthreads();
        #pragma unroll
        for (int u = 0; u < 4; u++) {
            int jj = (w << 2) + u;
            const float* row = &sP[b][jj * 128];
            unsigned long long acc0 = 0ull, acc1 = 0ull;
            #pragma unroll
            for (int k = 0; k < 4; k++) {
                F4U2 p; p.f = *(const float4*)&row[4 * (s + 8 * k)];
                ffma2(acc0, p.u[0], W0p[2 * k + 0]);
                ffma2(acc0, p.u[1], W0p[2 * k + 1]);
                ffma2(acc1, p.u[0], W1p[2 * k + 0]);
                ffma2(acc1, p.u[1], W1p[2 * k + 1]);
            }
            float a0 = hadd2(acc0), a1 = hadd2(acc1);
            #pragma unroll
            for (int o = 1; o < 8; o <<= 1) {
                a0 += __shfl_xor_sync(0xffffffffu, a0, o);
                a1 += __shfl_xor_sync(0xffffffffu, a1, o);
            }
            if (s == 0) {
                int j = jt + jj;
                sL[h0 * LP + j] += a0 * kScalePair + bb0;
                sL[h1 * LP + j] += a1 * kScalePair + bb1;
            }
        }
        __syncthreads();
    }

    // softmax: warp w owns head w
    {
        float* row = &sL[w * LP];
        float m = -1e30f;
        for (int j = lane; j < NN; j += 32) m = fmaxf(m, row[j]);
        #pragma unroll
        for (int o = 16; o; o >>= 1) m = fmaxf(m, __shfl_xor_sync(0xffffffffu, m, o));
        float sum = 0.f;
        for (int j = lane; j < NN; j += 32) {
            float e = __expf(row[j] - m);
            row[j] = e;
            sum += e;
        }
        #pragma unroll
        for (int o = 16; o; o >>= 1) sum += __shfl_xor_sync(0xffffffffu, sum, o);
        float inv = 1.f / sum;
        for (int j = lane; j < NN; j += 32) row[j] *= inv;
    }
    __syncthreads();

    // write weights to g_attn (coalesced)
    {
        float* dst = g_attn + (size_t)i * H * NN;
        #pragma unroll
        for (int m = 0; m < 4; m++) {
            int idx = t + 256 * m;
            int hh = idx >> 7, j4 = idx & 127;
            *(float4*)&dst[4 * idx] = *(const float4*)&sL[hh * LP + 4 * j4];
        }
    }
}

// ---------------------------------------------------------------------------
// Kernel 6: AV GEMM + epilogue.  Grid (8 it, 8 h); block: C[64 i][40 d], K=512.
// ---------------------------------------------------------------------------
__global__ __launch_bounds__(256) void av_kernel(const float* __restrict__ rot,
                                                 const float* __restrict__ trans)
{
    const int h = blockIdx.y;
    const int i0 = blockIdx.x * 64;
    const int t = threadIdx.x;
    const int ti = t >> 2, tg = t & 3;

    __shared__ float sA[64][33];
    __shared__ float sV[40][33];
    __shared__ float sC[64][41];

    float acc[10];
    #pragma unroll
    for (int q = 0; q < 10; q++) acc[q] = 0.f;

    for (int jt = 0; jt < NN; jt += 32) {
        __syncthreads();
        #pragma unroll
        for (int m = 0; m < 8; m++) {
            int idx = t + 256 * m;
            int il = idx >> 5, jj = idx & 31;
            sA[il][jj] = g_attn[(((size_t)i0 + il) * H + h) * NN + jt + jj];
        }
        #pragma unroll
        for (int m = 0; m < 5; m++) {
            int idx = t + 256 * m;
            int d = idx >> 5, jj = idx & 31;
            sV[d][jj] = g_vcombT[((size_t)h * 40 + d) * NN + jt + jj];
        }
        __syncthreads();
        #pragma unroll 4
        for (int jj = 0; jj < 32; jj++) {
            float a = sA[ti][jj];
            #pragma unroll
            for (int q = 0; q < 10; q++) acc[q] += a * sV[tg * 10 + q][jj];
        }
    }
    __syncthreads();
    #pragma unroll
    for (int q = 0; q < 10; q++) sC[ti][tg * 10 + q] = acc[q];
    __syncthreads();

    #pragma unroll
    for (int m = 0; m < 4; m++) {
        int idx = t + 256 * m;
        int il = idx >> 4, d = idx & 15;
        g_res[((size_t)i0 + il) * RES_COLS + h * 16 + d] = sC[il][d];
    }
    #pragma unroll
    for (int m = 0; m < 2; m++) {
        int idx = t + 256 * m;
        int il = idx >> 3, pv = idx & 7;
        int i = i0 + il;
        float g0 = sC[il][16 + pv * 3 + 0] - trans[i * 3 + 0];
        float g1 = sC[il][16 + pv * 3 + 1] - trans[i * 3 + 1];
        float g2 = sC[il][16 + pv * 3 + 2] - trans[i * 3 + 2];
        const float* R = rot + i * 9;
        float n2 = EPSV;
        #pragma unroll
        for (int r = 0; r < 3; r++) {
            float lr = g0 * R[r * 3 + 0] + g1 * R[r * 3 + 1] + g2 * R[r * 3 + 2];
            g_res[(size_t)i * RES_COLS + 128 + h * 24 + pv * 3 + r] = lr;
            n2 += lr * lr;
        }
        g_res[(size_t)i * RES_COLS + 320 + h * 8 + pv] = sqrtf(n2);
    }
}

// ---------------------------------------------------------------------------
// Kernel 7: res_pair.  Block per i; warp = (head-group hg, row-eighth jh);
// f32x2 packed accumulation; SMEM partial reduce; direct store.
// ---------------------------------------------------------------------------
__global__ __launch_bounds__(256) void res_pair_kernel(const float* __restrict__ pairw)
{
    const int i = blockIdx.x;
    const int t = threadIdx.x;
    const int w = t >> 5, lane = t & 31;
    const int hg = w & 1;                 // heads 4hg .. 4hg+3
    const int jh = w >> 1;                // rows [8jh, 8jh+8) within tile

    __shared__ __align__(16) float sP[2][32 * 128];   // 32 KB
    __shared__ float sW[H * NN];                      // attn [h][j], 16 KB
    __shared__ float4 sPart[8][4][32];                // 16 KB partials

    {
        const float* src = g_attn + (size_t)i * H * NN;
        #pragma unroll
        for (int m = 0; m < 4; m++) {
            int idx = t + 256 * m;
            *(float4*)&sW[4 * idx] = *(const float4*)&src[4 * idx];
        }
    }
    const float* pairRow = pairw + (size_t)i * NN * PDIM;
    const float* w0 = &sW[(4 * hg + 0) * NN];
    const float* w1 = &sW[(4 * hg + 1) * NN];
    const float* w2 = &sW[(4 * hg + 2) * NN];
    const float* w3 = &sW[(4 * hg + 3) * NN];

    unsigned long long A0a = 0ull, A0b = 0ull, A1a = 0ull, A1b = 0ull;
    unsigned long long A2a = 0ull, A2b = 0ull, A3a = 0ull, A3b = 0ull;

    stage_pair_tile(sP[0], pairRow, 0, t);
    for (int jt = 0; jt < NN; jt += 32) {
        int b = (jt >> 5) & 1;
        if (jt + 32 < NN) { stage_pair_tile(sP[b ^ 1], pairRow, jt + 32, t); cp_wait<1>(); }
        else              { cp_wait<0>(); }
        __syncthreads();
        const float* base = &sP[b][(8 * jh) * 128 + 4 * lane];
        #pragma unroll
        for (int r = 0; r < 8; r++) {
            int j = jt + 8 * jh + r;
            F4U2 p; p.f = *(const float4*)&base[r * 128];
            unsigned long long G0 = pack2(w0[j], w0[j]);
            unsigned long long G1 = pack2(w1[j], w1[j]);
            unsigned long long G2 = pack2(w2[j], w2[j]);
            unsigned long long G3 = pack2(w3[j], w3[j]);
            ffma2(A0a, G0, p.u[0]); ffma2(A0b, G0, p.u[1]);
            ffma2(A1a, G1, p.u[0]); ffma2(A1b, G1, p.u[1]);
            ffma2(A2a, G2, p.u[0]); ffma2(A2b, G2, p.u[1]);
            ffma2(A3a, G3, p.u[0]); ffma2(A3b, G3, p.u[1]);
        }
        __syncthreads();
    }

    {
        F4U2 v0; v0.u[0] = A0a; v0.u[1] = A0b;
        F4U2 v1; v1.u[0] = A1a; v1.u[1] = A1b;
        F4U2 v2; v2.u[0] = A2a; v2.u[1] = A2b;
        F4U2 v3; v3.u[0] = A3a; v3.u[1] = A3b;
        sPart[w][0][lane] = v0.f;
        sPart[w][1][lane] = v1.f;
        sPart[w][2][lane] = v2.f;
        sPart[w][3][lane] = v3.f;
    }
    __syncthreads();

    // thread t = h*32 + d4: sum 4 row-eighth partials
    {
        int h = t >> 5, d4 = t & 31;
        int hgq = h >> 2, hh = h & 3;
        float4 r = make_float4(0.f, 0.f, 0.f, 0.f);
        #pragma unroll
        for (int q = 0; q < 4; q++) {
            float4 p = sPart[2 * q + hgq][hh][d4];
            r.x += p.x; r.y += p.y; r.z += p.z; r.w += p.w;
        }
        *(float4*)&g_res[(size_t)i * RES_COLS + 384 + h * 128 + 4 * d4] = r;
    }
}

// ---------------------------------------------------------------------------
// Kernel 8: init output with bias (for split-K atomic GEMM)
// ---------------------------------------------------------------------------
__global__ void init_out_kernel(float* __restrict__ out, const float* __restrict__ bout)
{
    int idx = blockIdx.x * blockDim.x + threadIdx.x;
    if (idx < NN * DIM) out[idx] = bout[idx % DIM];
}

// ---------------------------------------------------------------------------
extern "C" void kernel_launch(void* const* d_in, const int* in_sizes, int n_in,
                              void* d_out, int out_size)
{
    const float* x      = (const float*)d_in[0];
    const float* pairw  = (const float*)d_in[1];
    const float* rot    = (const float*)d_in[2];
    const float* trans  = (const float*)d_in[3];
    const float* Wsq    = (const float*)d_in[4];
    const float* Wsk    = (const float*)d_in[5];
    const float* Wsv    = (const float*)d_in[6];
    const float* Wpq    = (const float*)d_in[7];
    const float* Wpk    = (const float*)d_in[8];
    const float* Wpv    = (const float*)d_in[9];
    const float* pw     = (const float*)d_in[10];
    const float* Wpair  = (const float*)d_in[11];
    const float* bpair  = (const float*)d_in[12];
    const float* Wout   = (const float*)d_in[13];
    const float* bout   = (const float*)d_in[14];
    float* out = (float*)d_out;

    float *pWcat, *pProj, *pRes;
    cudaGetSymbolAddress((void**)&pWcat, g_Wcat);
    cudaGetSymbolAddress((void**)&pProj, g_proj);
    cudaGetSymbolAddress((void**)&pRes,  g_res);

    // 1. concat weights
    concat_w_kernel<<<(DIM * PROJ_COLS + 255) / 256, 256>>>(Wsq, Wsk, Wsv, Wpq, Wpk, Wpv);

    // 2. projections: proj[512,768] = x @ Wcat
    gemm64_kernel<<<dim3(PROJ_COLS / 64, NN / 64), 256>>>(x, pWcat, pProj,
                                                          NN, PROJ_COLS, DIM, DIM, 0);

    // 3. build QA/KB/vcombT
    transform_kernel<<<(H * NN) / 256, 256>>>(rot, trans, pw);

    // 4. QK logits (scalar + point) via K=32 GEMM -> g_lp
    logit_gemm_kernel<<<dim3(8, 8, 8), 256>>>();

    // 5. pair-bias logits + softmax fused (first pairwise stream) -> g_attn
    pair_logits_sm_kernel<<<NN, 256>>>(pairw, Wpair, bpair);

    // 6. AV GEMM (res_scalar + res_point + norms)
    av_kernel<<<dim3(8, 8), 256>>>(rot, trans);

    // 7. res_pair (second pairwise stream)
    res_pair_kernel<<<NN, 256>>>(pairw);

    // 8-9. out = res @ Wout + bout   (split-K=4, atomic)
    init_out_kernel<<<(NN * DIM + 255) / 256, 256>>>(out, bout);
    gemm64_kernel<<<dim3(DIM / 64, NN / 64, 4), 256>>>(pRes, Wout, out,
                                                       NN, DIM, RES_COLS, 352, 1);
}

// round 13
// speedup vs baseline: 1.2287x; 1.0092x over previous
#include <cuda_runtime.h>
#include <cuda_bf16.h>
#include <cstdint>
#include <math.h>

// Problem constants
#define NN 512
#define DIM 384
#define PDIM 128
#define H 8
#define SK 16
#define SV 16
#define PK 4
#define PV 8
#define PROJ_COLS 768           // 128+128+128+96+96+192
#define RES_COLS 1408           // 128 + 192 + 64 + 1024
#define EPSV 1e-8f
#define LP 516                  // sL pitch (floats)

__device__ __constant__ float kScaleScalar = 0.14433756729740643f;  // (3*16)^-0.5
__device__ __constant__ float kScalePoint  = 0.13608276348795434f;  // (3*4*4.5)^-0.5
__device__ __constant__ float kScalePair   = 0.57735026918962576f;  // 3^-0.5

// Scratch (allocation-free contract: __device__ globals)
__device__ float g_Wcat[DIM * PROJ_COLS];
__device__ float g_proj[NN * PROJ_COLS];
__device__ float g_QA[H * NN * 32];          // per-head q features [h][i][32]
__device__ float g_KB[H * NN * 32];          // per-head k features [h][j][32]
__device__ float g_vcombT[H * 40 * NN];      // per-head v (16 scalar + 24 point), [h][d][j]
__device__ float g_lp[NN * H * NN];          // QK logits [i][h][j]
__device__ float g_attn[NN * H * NN];        // normalized attn weights [i][h][j]
__device__ float g_res[NN * RES_COLS];

// ---------------------------------------------------------------------------
// packed f32x2 helpers (2 fp32 MACs per instruction; exact fp32 semantics)
// ---------------------------------------------------------------------------
__device__ __forceinline__ void ffma2(unsigned long long& acc,
                                      unsigned long long a, unsigned long long b) {
    asm("fma.rn.f32x2 %0, %1, %2, %0;" : "+l"(acc) : "l"(a), "l"(b));
}
__device__ __forceinline__ unsigned long long pack2(float lo, float hi) {
    unsigned long long r;
    asm("mov.b64 %0, {%1, %2};" : "=l"(r) : "f"(lo), "f"(hi));
    return r;
}
__device__ __forceinline__ float hadd2(unsigned long long v) {
    float lo, hi;
    asm("mov.b64 {%0, %1}, %2;" : "=f"(lo), "=f"(hi) : "l"(v));
    return lo + hi;
}
union F4U2 { float4 f; unsigned long long u[2]; };

// ---------------------------------------------------------------------------
// TF32 MMA helpers
// ---------------------------------------------------------------------------
__device__ __forceinline__ uint32_t cvt_tf32(float v) {
    uint32_t r;
    asm("cvt.rna.tf32.f32 %0, %1;" : "=r"(r) : "f"(v));
    return r;
}
__device__ __forceinline__ void mma_tf32(float* c, uint32_t a0, uint32_t a1,
                                         uint32_t a2, uint32_t a3,
                                         uint32_t b0, uint32_t b1) {
    asm volatile(
        "mma.sync.aligned.m16n8k8.row.col.f32.tf32.tf32.f32 "
        "{%0,%1,%2,%3}, {%4,%5,%6,%7}, {%8,%9}, {%0,%1,%2,%3};"
        : "+f"(c[0]), "+f"(c[1]), "+f"(c[2]), "+f"(c[3])
        : "r"(a0), "r"(a1), "r"(a2), "r"(a3), "r"(b0), "r"(b1));
}

// ---------------------------------------------------------------------------
// cp.async helpers (.cg = L2-only, data is touch-once)
// ---------------------------------------------------------------------------
__device__ __forceinline__ void cp_async16(void* smem_dst, const void* gmem_src) {
    uint32_t dst = (uint32_t)__cvta_generic_to_shared(smem_dst);
    asm volatile("cp.async.cg.shared.global [%0], [%1], 16;" :: "r"(dst), "l"(gmem_src));
}
__device__ __forceinline__ void cp_commit() {
    asm volatile("cp.async.commit_group;");
}
template <int N>
__device__ __forceinline__ void cp_wait() {
    asm volatile("cp.async.wait_group %0;" :: "n"(N));
}

// Stage one contiguous 32j x 128d pair tile (16 KB) with cp.async; 256 threads.
__device__ __forceinline__ void stage_pair_tile(float* sbuf, const float* pairRow,
                                                int j0, int t)
{
    const float* src = pairRow + (size_t)j0 * PDIM;
    #pragma unroll
    for (int m = 0; m < 4; m++) {
        int idx = t + 256 * m;           // 0..1023 float4 slots
        cp_async16(&sbuf[4 * idx], src + 4 * idx);
    }
    cp_commit();
}

// ---------------------------------------------------------------------------
// Kernel 1: concat projection weights into [384 x 768]
// ---------------------------------------------------------------------------
__global__ void concat_w_kernel(const float* __restrict__ Wsq, const float* __restrict__ Wsk,
                                const float* __restrict__ Wsv, const float* __restrict__ Wpq,
                                const float* __restrict__ Wpk, const float* __restrict__ Wpv)
{
    int idx = blockIdx.x * blockDim.x + threadIdx.x;
    if (idx >= DIM * PROJ_COLS) return;
    int k = idx / PROJ_COLS;
    int c = idx - k * PROJ_COLS;
    float v;
    if (c < 128)       v = Wsq[k * 128 + c];
    else if (c < 256)  v = Wsk[k * 128 + (c - 128)];
    else if (c < 384)  v = Wsv[k * 128 + (c - 256)];
    else if (c < 480)  v = Wpq[k * 96 + (c - 384)];
    else if (c < 576)  v = Wpk[k * 96 + (c - 480)];
    else               v = Wpv[k * 192 + (c - 576)];
    g_Wcat[idx] = v;
}

// ---------------------------------------------------------------------------
// 64x64 tiled fp32 GEMM, 4x4 microtile, BK=16, f32x2 packed inner loop.
// ---------------------------------------------------------------------------
__global__ __launch_bounds__(256) void gemm64_kernel(const float* __restrict__ A,
                                                     const float* __restrict__ B,
                                                     float* __restrict__ C,
                                                     int M, int N, int K,
                                                     int kChunk, int useAtomic)
{
    __shared__ float As[16][68];   // [k][m]
    __shared__ float Bs[16][68];   // [k][n]
    const int bm = blockIdx.y * 64;
    const int bn = blockIdx.x * 64;
    int k0 = blockIdx.z * kChunk;
    int k1 = k0 + kChunk; if (k1 > K) k1 = K;
    const int t  = threadIdx.x;
    const int tx = t & 15, ty = t >> 4;

    const int lm  = t >> 2;
    const int lk4 = (t & 3) * 4;
    const int lkb = t >> 4;
    const int lnb = (t & 15) * 4;

    unsigned long long accU[4][2];
    #pragma unroll
    for (int r = 0; r < 4; r++) { accU[r][0] = 0ull; accU[r][1] = 0ull; }

    for (int kt = k0; kt < k1; kt += 16) {
        float4 a4 = *(const float4*)&A[(size_t)(bm + lm) * K + kt + lk4];
        float4 b4 = *(const float4*)&B[(size_t)(kt + lkb) * N + bn + lnb];
        __syncthreads();
        As[lk4 + 0][lm] = a4.x; As[lk4 + 1][lm] = a4.y;
        As[lk4 + 2][lm] = a4.z; As[lk4 + 3][lm] = a4.w;
        *(float4*)&Bs[lkb][lnb] = b4;
        __syncthreads();
        #pragma unroll
        for (int kk = 0; kk < 16; kk++) {
            float4 av = *(const float4*)&As[kk][ty * 4];
            F4U2 bv; bv.f = *(const float4*)&Bs[kk][tx * 4];
            unsigned long long ax = pack2(av.x, av.x);
            unsigned long long ay = pack2(av.y, av.y);
            unsigned long long az = pack2(av.z, av.z);
            unsigned long long aw = pack2(av.w, av.w);
            ffma2(accU[0][0], ax, bv.u[0]); ffma2(accU[0][1], ax, bv.u[1]);
            ffma2(accU[1][0], ay, bv.u[0]); ffma2(accU[1][1], ay, bv.u[1]);
            ffma2(accU[2][0], az, bv.u[0]); ffma2(accU[2][1], az, bv.u[1]);
            ffma2(accU[3][0], aw, bv.u[0]); ffma2(accU[3][1], aw, bv.u[1]);
        }
    }
    #pragma unroll
    for (int r = 0; r < 4; r++) {
        F4U2 v; v.u[0] = accU[r][0]; v.u[1] = accU[r][1];
        float* cp = &C[(size_t)(bm + ty * 4 + r) * N + bn + tx * 4];
        if (useAtomic) {
            atomicAdd(cp + 0, v.f.x); atomicAdd(cp + 1, v.f.y);
            atomicAdd(cp + 2, v.f.z); atomicAdd(cp + 3, v.f.w);
        } else {
            *(float4*)cp = v.f;
        }
    }
}

// ---------------------------------------------------------------------------
// Kernel 3: build per-head GEMM operand matrices.
// ---------------------------------------------------------------------------
__global__ void transform_kernel(const float* __restrict__ rot, const float* __restrict__ trans,
                                 const float* __restrict__ point_weights)
{
    int tid = blockIdx.x * blockDim.x + threadIdx.x;
    if (tid >= H * NN) return;
    int h = tid >> 9, n = tid & 511;
    float pwh = log1pf(__expf(point_weights[h]));
    float cP = -0.5f * pwh * kScalePoint;
    const float* R = rot + n * 9;
    const float t0 = trans[n * 3 + 0], t1 = trans[n * 3 + 1], t2 = trans[n * 3 + 2];
    const float* pr = g_proj + (size_t)n * PROJ_COLS;
    float* qa = g_QA + ((size_t)h * NN + n) * 32;
    float* kb = g_KB + ((size_t)h * NN + n) * 32;

    #pragma unroll
    for (int d = 0; d < 16; d++) {
        qa[d] = pr[h * 16 + d] * kScaleScalar;
        kb[d] = pr[128 + h * 16 + d];
    }
    float qq = 0.f, kk = 0.f;
    #pragma unroll
    for (int pd = 0; pd < 4; pd++) {
        const float* q = pr + 384 + h * 12 + pd * 3;
        float g0 = q[0] * R[0] + q[1] * R[3] + q[2] * R[6] + t0;
        float g1 = q[0] * R[1] + q[1] * R[4] + q[2] * R[7] + t1;
        float g2 = q[0] * R[2] + q[1] * R[5] + q[2] * R[8] + t2;
        qa[16 + pd * 3 + 0] = -2.f * cP * g0;
        qa[16 + pd * 3 + 1] = -2.f * cP * g1;
        qa[16 + pd * 3 + 2] = -2.f * cP * g2;
        qq += g0 * g0 + g1 * g1 + g2 * g2;
        const float* k = pr + 480 + h * 12 + pd * 3;
        float f0 = k[0] * R[0] + k[1] * R[3] + k[2] * R[6] + t0;
        float f1 = k[0] * R[1] + k[1] * R[4] + k[2] * R[7] + t1;
        float f2 = k[0] * R[2] + k[1] * R[5] + k[2] * R[8] + t2;
        kb[16 + pd * 3 + 0] = f0;
        kb[16 + pd * 3 + 1] = f1;
        kb[16 + pd * 3 + 2] = f2;
        kk += f0 * f0 + f1 * f1 + f2 * f2;
    }
    qa[28] = cP * qq; qa[29] = 1.f; qa[30] = 0.f; qa[31] = 0.f;
    kb[28] = 1.f; kb[29] = cP * kk; kb[30] = 0.f; kb[31] = 0.f;

    #pragma unroll
    for (int d = 0; d < 16; d++)
        g_vcombT[((size_t)h * 40 + d) * NN + n] = pr[256 + h * 16 + d];
    #pragma unroll
    for (int pv = 0; pv < 8; pv++) {
        const float* v = pr + 576 + h * 24 + pv * 3;
        float g0 = v[0] * R[0] + v[1] * R[3] + v[2] * R[6] + t0;
        float g1 = v[0] * R[1] + v[1] * R[4] + v[2] * R[7] + t1;
        float g2 = v[0] * R[2] + v[1] * R[5] + v[2] * R[8] + t2;
        g_vcombT[((size_t)h * 40 + 16 + pv * 3 + 0) * NN + n] = g0;
        g_vcombT[((size_t)h * 40 + 16 + pv * 3 + 1) * NN + n] = g1;
        g_vcombT[((size_t)h * 40 + 16 + pv * 3 + 2) * NN + n] = g2;
    }
}

// ---------------------------------------------------------------------------
// Kernel 4: QK logit GEMM.  g_lp[i][h][j] = QA[h][i] . KB[h][j]
// Grid (8 jt, 8 it, 8 h); 64i x 64j, K=32, f32x2 packed.
// ---------------------------------------------------------------------------
__global__ __launch_bounds__(256) void logit_gemm_kernel()
{
    const int h = blockIdx.z;
    const int i0 = blockIdx.y * 64;
    const int j0 = blockIdx.x * 64;
    __shared__ float sQ[32][68];   // [k][i]
    __shared__ float sK[32][68];   // [k][j]
    const int t = threadIdx.x, tx = t & 15, ty = t >> 4;

    #pragma unroll
    for (int m = 0; m < 8; m++) {
        int idx = t + 256 * m;
        int row = idx >> 5, k = idx & 31;
        sQ[k][row] = g_QA[((size_t)h * NN + i0 + row) * 32 + k];
        sK[k][row] = g_KB[((size_t)h * NN + j0 + row) * 32 + k];
    }
    __syncthreads();

    unsigned long long accU[4][2];
    #pragma unroll
    for (int r = 0; r < 4; r++) { accU[r][0] = 0ull; accU[r][1] = 0ull; }

    #pragma unroll
    for (int kk = 0; kk < 32; kk++) {
        float4 a = *(const float4*)&sQ[kk][ty * 4];
        F4U2 b; b.f = *(const float4*)&sK[kk][tx * 4];
        unsigned long long ax = pack2(a.x, a.x);
        unsigned long long ay = pack2(a.y, a.y);
        unsigned long long az = pack2(a.z, a.z);
        unsigned long long aw = pack2(a.w, a.w);
        ffma2(accU[0][0], ax, b.u[0]); ffma2(accU[0][1], ax, b.u[1]);
        ffma2(accU[1][0], ay, b.u[0]); ffma2(accU[1][1], ay, b.u[1]);
        ffma2(accU[2][0], az, b.u[0]); ffma2(accU[2][1], az, b.u[1]);
        ffma2(accU[3][0], aw, b.u[0]); ffma2(accU[3][1], aw, b.u[1]);
    }
    #pragma unroll
    for (int r = 0; r < 4; r++) {
        F4U2 v; v.u[0] = accU[r][0]; v.u[1] = accU[r][1];
        *(float4*)&g_lp[(((size_t)i0 + ty * 4 + r) * H + h) * NN + j0 + tx * 4] = v.f;
    }
}

// ---------------------------------------------------------------------------
// Kernel 5: pair-bias logits + softmax (fused).  Block per i.
//   preload QK logits -> stream pairwise (cp.async double-buffer),
//   head-paired lanes, f32x2 packed contraction -> softmax -> g_attn.
// ---------------------------------------------------------------------------
__global__ __launch_bounds__(256) void pair_logits_sm_kernel(const float* __restrict__ pairw,
                                                             const float* __restrict__ Wpair,
                                                             const float* __restrict__ bpair)
{
    const int i = blockIdx.x;
    const int t = threadIdx.x;
    const int w = t >> 5, lane = t & 31;
    const int hp = lane >> 3;            // head pair 0..3 -> heads 2hp, 2hp+1
    const int s  = lane & 7;             // d-slice 0..7

    __shared__ __align__(16) float sP[2][32 * 128];   // 2 x 16 KB tiles
    __shared__ float sL[H * LP];                      // logits -> weights

    const int h0 = 2 * hp, h1 = 2 * hp + 1;
    unsigned long long W0p[8], W1p[8];
    #pragma unroll
    for (int k = 0; k < 4; k++) {
        int d0 = 4 * (s + 8 * k);
        W0p[2 * k + 0] = pack2(Wpair[(d0 + 0) * 8 + h0], Wpair[(d0 + 1) * 8 + h0]);
        W0p[2 * k + 1] = pack2(Wpair[(d0 + 2) * 8 + h0], Wpair[(d0 + 3) * 8 + h0]);
        W1p[2 * k + 0] = pack2(Wpair[(d0 + 0) * 8 + h1], Wpair[(d0 + 1) * 8 + h1]);
        W1p[2 * k + 1] = pack2(Wpair[(d0 + 2) * 8 + h1], Wpair[(d0 + 3) * 8 + h1]);
    }
    const float bb0 = bpair[h0] * kScalePair;
    const float bb1 = bpair[h1] * kScalePair;
    const float* pairRow = pairw + (size_t)i * NN * PDIM;

    // preload QK logits into sL
    {
        const float* src = g_lp + (size_t)i * H * NN;
        #pragma unroll
        for (int m = 0; m < 4; m++) {
            int idx = t + 256 * m;
            int hh = idx >> 7, j4 = idx & 127;
            *(float4*)&sL[hh * LP + 4 * j4] = *(const float4*)&src[4 * idx];
        }
    }

    stage_pair_tile(sP[0], pairRow, 0, t);
    __syncthreads();                       // sL preload visible before +=
    for (int jt = 0; jt < NN; jt += 32) {
        int b = (jt >> 5) & 1;
        if (jt + 32 < NN) { stage_pair_tile(sP[b ^ 1], pairRow, jt + 32, t); cp_wait<1>(); }
        else              { cp_wait<0>(); }
        __syncthreads();
        #pragma unroll
        for (int u = 0; u < 4; u++) {
            int jj = (w << 2) + u;
            const float* row = &sP[b][jj * 128];
            unsigned long long acc0 = 0ull, acc1 = 0ull;
            #pragma unroll
            for (int k = 0; k < 4; k++) {
                F4U2 p; p.f = *(const float4*)&row[4 * (s + 8 * k)];
                ffma2(acc0, p.u[0], W0p[2 * k + 0]);
                ffma2(acc0, p.u[1], W0p[2 * k + 1]);
                ffma2(acc1, p.u[0], W1p[2 * k + 0]);
                ffma2(acc1, p.u[1], W1p[2 * k + 1]);
            }
            float a0 = hadd2(acc0), a1 = hadd2(acc1);
            #pragma unroll
            for (int o = 1; o < 8; o <<= 1) {
                a0 += __shfl_xor_sync(0xffffffffu, a0, o);
                a1 += __shfl_xor_sync(0xffffffffu, a1, o);
            }
            if (s == 0) {
                int j = jt + jj;
                sL[h0 * LP + j] += a0 * kScalePair + bb0;
                sL[h1 * LP + j] += a1 * kScalePair + bb1;
            }
        }
        __syncthreads();
    }

    // softmax: warp w owns head w
    {
        float* row = &sL[w * LP];
        float m = -1e30f;
        for (int j = lane; j < NN; j += 32) m = fmaxf(m, row[j]);
        #pragma unroll
        for (int o = 16; o; o >>= 1) m = fmaxf(m, __shfl_xor_sync(0xffffffffu, m, o));
        float sum = 0.f;
        for (int j = lane; j < NN; j += 32) {
            float e = __expf(row[j] - m);
            row[j] = e;
            sum += e;
        }
        #pragma unroll
        for (int o = 16; o; o >>= 1) sum += __shfl_xor_sync(0xffffffffu, sum, o);
        float inv = 1.f / sum;
        for (int j = lane; j < NN; j += 32) row[j] *= inv;
    }
    __syncthreads();

    // write weights to g_attn (coalesced)
    {
        float* dst = g_attn + (size_t)i * H * NN;
        #pragma unroll
        for (int m = 0; m < 4; m++) {
            int idx = t + 256 * m;
            int hh = idx >> 7, j4 = idx & 127;
            *(float4*)&dst[4 * idx] = *(const float4*)&sL[hh * LP + 4 * j4];
        }
    }
}

// ---------------------------------------------------------------------------
// Kernel 6: AV GEMM + epilogue.  Grid (8 it, 8 h); block: C[64 i][40 d], K=512.
// ---------------------------------------------------------------------------
__global__ __launch_bounds__(256) void av_kernel(const float* __restrict__ rot,
                                                 const float* __restrict__ trans)
{
    const int h = blockIdx.y;
    const int i0 = blockIdx.x * 64;
    const int t = threadIdx.x;
    const int ti = t >> 2, tg = t & 3;

    __shared__ float sA[64][33];
    __shared__ float sV[40][33];
    __shared__ float sC[64][41];

    float acc[10];
    #pragma unroll
    for (int q = 0; q < 10; q++) acc[q] = 0.f;

    for (int jt = 0; jt < NN; jt += 32) {
        __syncthreads();
        #pragma unroll
        for (int m = 0; m < 8; m++) {
            int idx = t + 256 * m;
            int il = idx >> 5, jj = idx & 31;
            sA[il][jj] = g_attn[(((size_t)i0 + il) * H + h) * NN + jt + jj];
        }
        #pragma unroll
        for (int m = 0; m < 5; m++) {
            int idx = t + 256 * m;
            int d = idx >> 5, jj = idx & 31;
            sV[d][jj] = g_vcombT[((size_t)h * 40 + d) * NN + jt + jj];
        }
        __syncthreads();
        #pragma unroll 4
        for (int jj = 0; jj < 32; jj++) {
            float a = sA[ti][jj];
            #pragma unroll
            for (int q = 0; q < 10; q++) acc[q] += a * sV[tg * 10 + q][jj];
        }
    }
    __syncthreads();
    #pragma unroll
    for (int q = 0; q < 10; q++) sC[ti][tg * 10 + q] = acc[q];
    __syncthreads();

    #pragma unroll
    for (int m = 0; m < 4; m++) {
        int idx = t + 256 * m;
        int il = idx >> 4, d = idx & 15;
        g_res[((size_t)i0 + il) * RES_COLS + h * 16 + d] = sC[il][d];
    }
    #pragma unroll
    for (int m = 0; m < 2; m++) {
        int idx = t + 256 * m;
        int il = idx >> 3, pv = idx & 7;
        int i = i0 + il;
        float g0 = sC[il][16 + pv * 3 + 0] - trans[i * 3 + 0];
        float g1 = sC[il][16 + pv * 3 + 1] - trans[i * 3 + 1];
        float g2 = sC[il][16 + pv * 3 + 2] - trans[i * 3 + 2];
        const float* R = rot + i * 9;
        float n2 = EPSV;
        #pragma unroll
        for (int r = 0; r < 3; r++) {
            float lr = g0 * R[r * 3 + 0] + g1 * R[r * 3 + 1] + g2 * R[r * 3 + 2];
            g_res[(size_t)i * RES_COLS + 128 + h * 24 + pv * 3 + r] = lr;
            n2 += lr * lr;
        }
        g_res[(size_t)i * RES_COLS + 320 + h * 8 + pv] = sqrtf(n2);
    }
}

// ---------------------------------------------------------------------------
// Kernel 7: res_pair via TF32 tensor-core MMA.  Block per i.
//   out[8h x 128d] = attn[8 x 512] @ pair[512 x 128], M padded to 16.
//   Warp w owns d in [16w, 16w+16) (two m16n8k8 n-tiles); K=512 entirely
//   in-warp -> no cross-warp reduction; direct float2 stores from C frags.
// ---------------------------------------------------------------------------
__global__ __launch_bounds__(256) void res_pair_kernel(const float* __restrict__ pairw)
{
    const int i = blockIdx.x;
    const int t = threadIdx.x;
    const int w = t >> 5, lane = t & 31;

    __shared__ __align__(16) float sP[2][32 * 128];   // 32 KB pair tiles
    __shared__ __align__(16) float sA[8 * 516];       // attn [h][j], pitch 516

    // load attn (pitch 516 => A-fragment LDS bank = (4h + j)&31, conflict-free)
    {
        const float* src = g_attn + (size_t)i * H * NN;
        #pragma unroll
        for (int m = 0; m < 4; m++) {
            int idx = t + 256 * m;
            int hh = idx >> 7, j4 = idx & 127;
            *(float4*)&sA[hh * 516 + 4 * j4] = *(const float4*)&src[4 * idx];
        }
    }
    const float* pairRow = pairw + (size_t)i * NN * PDIM;

    const int n0 = w * 16;               // warp's d-range
    const int aj = lane & 3;             // fragment k-col
    const int ah = lane >> 2;            // fragment row (head)
    const int bd0 = n0 + (lane >> 2);    // B col for n-tile 0
    const int bd1 = bd0 + 8;             // B col for n-tile 1

    float c0[4] = {0.f, 0.f, 0.f, 0.f};
    float c1[4] = {0.f, 0.f, 0.f, 0.f};

    stage_pair_tile(sP[0], pairRow, 0, t);
    for (int jt = 0; jt < NN; jt += 32) {
        int b = (jt >> 5) & 1;
        if (jt + 32 < NN) { stage_pair_tile(sP[b ^ 1], pairRow, jt + 32, t); cp_wait<1>(); }
        else              { cp_wait<0>(); }
        __syncthreads();
        const float* P = sP[b];
        const float* Arow = &sA[ah * 516 + jt + aj];
        #pragma unroll
        for (int kt = 0; kt < 32; kt += 8) {
            uint32_t a0 = cvt_tf32(Arow[kt]);
            uint32_t a2 = cvt_tf32(Arow[kt + 4]);
            uint32_t b00 = cvt_tf32(P[(kt + aj) * 128 + bd0]);
            uint32_t b01 = cvt_tf32(P[(kt + aj + 4) * 128 + bd0]);
            mma_tf32(c0, a0, 0u, a2, 0u, b00, b01);
            uint32_t b10 = cvt_tf32(P[(kt + aj) * 128 + bd1]);
            uint32_t b11 = cvt_tf32(P[(kt + aj + 4) * 128 + bd1]);
            mma_tf32(c1, a0, 0u, a2, 0u, b10, b11);
        }
        __syncthreads();
    }

    // epilogue: c[0],c[1] -> (h = ah, d = n-tile base + 2*(lane&3) [+1]);
    // c[2],c[3] are padded rows 8..15, discarded.
    {
        int dc = (lane & 3) * 2;
        float* dst = &g_res[(size_t)i * RES_COLS + 384 + ah * 128];
        *(float2*)&dst[n0 + dc]     = make_float2(c0[0], c0[1]);
        *(float2*)&dst[n0 + 8 + dc] = make_float2(c1[0], c1[1]);
    }
}

// ---------------------------------------------------------------------------
// Kernel 8: init output with bias (for split-K atomic GEMM)
// ---------------------------------------------------------------------------
__global__ void init_out_kernel(float* __restrict__ out, const float* __restrict__ bout)
{
    int idx = blockIdx.x * blockDim.x + threadIdx.x;
    if (idx < NN * DIM) out[idx] = bout[idx % DIM];
}

// ---------------------------------------------------------------------------
extern "C" void kernel_launch(void* const* d_in, const int* in_sizes, int n_in,
                              void* d_out, int out_size)
{
    const float* x      = (const float*)d_in[0];
    const float* pairw  = (const float*)d_in[1];
    const float* rot    = (const float*)d_in[2];
    const float* trans  = (const float*)d_in[3];
    const float* Wsq    = (const float*)d_in[4];
    const float* Wsk    = (const float*)d_in[5];
    const float* Wsv    = (const float*)d_in[6];
    const float* Wpq    = (const float*)d_in[7];
    const float* Wpk    = (const float*)d_in[8];
    const float* Wpv    = (const float*)d_in[9];
    const float* pw     = (const float*)d_in[10];
    const float* Wpair  = (const float*)d_in[11];
    const float* bpair  = (const float*)d_in[12];
    const float* Wout   = (const float*)d_in[13];
    const float* bout   = (const float*)d_in[14];
    float* out = (float*)d_out;

    float *pWcat, *pProj, *pRes;
    cudaGetSymbolAddress((void**)&pWcat, g_Wcat);
    cudaGetSymbolAddress((void**)&pProj, g_proj);
    cudaGetSymbolAddress((void**)&pRes,  g_res);

    // 1. concat weights
    concat_w_kernel<<<(DIM * PROJ_COLS + 255) / 256, 256>>>(Wsq, Wsk, Wsv, Wpq, Wpk, Wpv);

    // 2. projections: proj[512,768] = x @ Wcat
    gemm64_kernel<<<dim3(PROJ_COLS / 64, NN / 64), 256>>>(x, pWcat, pProj,
                                                          NN, PROJ_COLS, DIM, DIM, 0);

    // 3. build QA/KB/vcombT
    transform_kernel<<<(H * NN) / 256, 256>>>(rot, trans, pw);

    // 4. QK logits (scalar + point) via K=32 GEMM -> g_lp
    logit_gemm_kernel<<<dim3(8, 8, 8), 256>>>();

    // 5. pair-bias logits + softmax fused (first pairwise stream) -> g_attn
    pair_logits_sm_kernel<<<NN, 256>>>(pairw, Wpair, bpair);

    // 6. AV GEMM (res_scalar + res_point + norms)
    av_kernel<<<dim3(8, 8), 256>>>(rot, trans);

    // 7. res_pair via TF32 MMA (second pairwise stream)
    res_pair_kernel<<<NN, 256>>>(pairw);

    // 8-9. out = res @ Wout + bout   (split-K=4, atomic)
    init_out_kernel<<<(NN * DIM + 255) / 256, 256>>>(out, bout);
    gemm64_kernel<<<dim3(DIM / 64, NN / 64, 4), 256>>>(pRes, Wout, out,
                                                       NN, DIM, RES_COLS, 352, 1);
}